// round 14
// baseline (speedup 1.0000x reference)
#include <cuda_runtime.h>

typedef unsigned long long u64;

// ---------------- DOPRI5 coefficients ----------------
__constant__ float cA[15] = {
    (float)(1.0/5.0),
    (float)(3.0/40.0), (float)(9.0/40.0),
    (float)(44.0/45.0), (float)(-56.0/15.0), (float)(32.0/9.0),
    (float)(19372.0/6561.0), (float)(-25360.0/2187.0), (float)(64448.0/6561.0), (float)(-212.0/729.0),
    (float)(9017.0/3168.0), (float)(-355.0/33.0), (float)(46732.0/5247.0), (float)(49.0/176.0), (float)(-5103.0/18656.0)
};
__constant__ float cB[6] = {
    (float)(35.0/384.0), 0.0f, (float)(500.0/1113.0),
    (float)(125.0/192.0), (float)(-2187.0/6784.0), (float)(11.0/84.0)
};
__constant__ float cC[6] = { 0.0f, (float)(1.0/5.0), (float)(3.0/10.0),
                             (float)(4.0/5.0), (float)(8.0/9.0), 1.0f };

// ---------------- f32x2 helpers ----------------
__device__ __forceinline__ u64 pk2(float lo, float hi) {
    u64 r; asm("mov.b64 %0, {%1, %2};" : "=l"(r) : "f"(lo), "f"(hi)); return r;
}
__device__ __forceinline__ void upk2(u64 v, float& lo, float& hi) {
    asm("mov.b64 {%0, %1}, %2;" : "=f"(lo), "=f"(hi) : "l"(v));
}
__device__ __forceinline__ u64 fma2_(u64 a, u64 b, u64 c) {
    u64 d; asm("fma.rn.f32x2 %0, %1, %2, %3;" : "=l"(d) : "l"(a), "l"(b), "l"(c)); return d;
}
__device__ __forceinline__ float2 f2fma(float a, float2 b, float2 c) {
    return make_float2(fmaf(a, b.x, c.x), fmaf(a, b.y, c.y));
}

// two tanhs in ONE MUFU op via tanh.approx.f16x2; fp32 gates in, fp32 accumulation out.
// Per-particle numerics identical to R7 (measured end-to-end rel_err 5.78e-4).
__device__ __forceinline__ u64 tanh2h_(u64 g) {
    float lo, hi; upk2(g, lo, hi);
    unsigned int hp, ht;
    asm("cvt.rn.f16x2.f32 %0, %1, %2;" : "=r"(hp) : "f"(hi), "f"(lo));
    asm("tanh.approx.f16x2 %0, %1;" : "=r"(ht) : "r"(hp));
    float rlo, rhi;
    asm("{ .reg .b16 l, h;\n\t"
        "  mov.b32 {l, h}, %2;\n\t"
        "  cvt.f32.f16 %0, l;\n\t"
        "  cvt.f32.f16 %1, h; }"
        : "=f"(rlo), "=f"(rhi) : "r"(ht));
    return pk2(rlo, rhi);
}

// ---------------- dynamics for a particle pair ----------------
// sw[j][0..15] = duplicated-f32x2 weights:
//   0:W1[j,0] 1:W1[j,1] 2:wb1 3:bb1 4:Wo1  5:W2[j,0] 6:W2[j,1] 7:wb2 8:bb2 9:Wo2
//   10:W3[j,0] 11:W3[j,1] 12:W3[j,2] 13:wb3 14:bb3 15:Wo3
__device__ __forceinline__ void dyn2(float t, float2 X0, float2 X1, float2 X2,
                                     float2* kk, const u64 (*sw)[16]) {
    u64 x0 = pk2(X0.x, X0.y);
    u64 x1 = pk2(X1.x, X1.y);
    u64 x2 = pk2(X2.x, X2.y);
    u64 tt = pk2(t, t);
    u64 a1 = 0ULL, a2 = 0ULL, a3 = 0ULL;

    #pragma unroll 4
    for (int j = 0; j < 64; j++) {
        const ulonglong2* p = reinterpret_cast<const ulonglong2*>(sw[j]);
        ulonglong2 q0 = p[0], q1 = p[1], q2 = p[2], q3 = p[3];
        ulonglong2 q4 = p[4], q5 = p[5], q6 = p[6], q7 = p[7];

        // net 1: z @ W1.T + wb1*t + bb1
        u64 g1 = fma2_(q1.x, tt, q1.y);
        g1 = fma2_(q0.x, x0, g1);
        g1 = fma2_(q0.y, x1, g1);
        a1 = fma2_(q2.x, tanh2h_(g1), a1);

        // net 2
        u64 g2 = fma2_(q3.y, tt, q4.x);
        g2 = fma2_(q2.y, x0, g2);
        g2 = fma2_(q3.x, x1, g2);
        a2 = fma2_(q4.y, tanh2h_(g2), a2);

        // net 3 (3 state inputs)
        u64 g3 = fma2_(q6.y, tt, q7.x);
        g3 = fma2_(q5.x, x0, g3);
        g3 = fma2_(q5.y, x1, g3);
        g3 = fma2_(q6.x, x2, g3);
        a3 = fma2_(q7.y, tanh2h_(g3), a3);
    }
    float lo, hi;
    upk2(a1, lo, hi); kk[0] = make_float2(lo, hi);
    upk2(a2, lo, hi); kk[1] = make_float2(lo, hi);
    upk2(a3, lo, hi); kk[2] = make_float2(lo, hi);
}

// ---------------- main kernel: 2 particles/thread, phase split, max warp count ----------------
extern "C" __global__ void __launch_bounds__(128, 4)
ode_kernel(const float* __restrict__ u,
           const float* __restrict__ W1, const float* __restrict__ W2, const float* __restrict__ W3,
           const float* __restrict__ wb1, const float* __restrict__ bb1,
           const float* __restrict__ wb2, const float* __restrict__ bb2,
           const float* __restrict__ wb3, const float* __restrict__ bb3,
           const float* __restrict__ Wo1, const float* __restrict__ Wo2, const float* __restrict__ Wo3,
           float* __restrict__ out, int B)
{
    __shared__ __align__(16) u64 sw[64][16];
    int tid = threadIdx.x;
    for (int idx = tid; idx < 64 * 16; idx += blockDim.x) {
        int j = idx >> 4, f = idx & 15;
        float v;
        switch (f) {
            case 0:  v = W1[2*j];    break;
            case 1:  v = W1[2*j+1];  break;
            case 2:  v = wb1[j];     break;
            case 3:  v = bb1[j];     break;
            case 4:  v = Wo1[j];     break;
            case 5:  v = W2[2*j];    break;
            case 6:  v = W2[2*j+1];  break;
            case 7:  v = wb2[j];     break;
            case 8:  v = bb2[j];     break;
            case 9:  v = Wo2[j];     break;
            case 10: v = W3[3*j];    break;
            case 11: v = W3[3*j+1];  break;
            case 12: v = W3[3*j+2];  break;
            case 13: v = wb3[j];     break;
            case 14: v = bb3[j];     break;
            default: v = Wo3[j];     break;
        }
        sw[j][f] = pk2(v, v);
    }
    __syncthreads();

    const int npairs = B >> 1;
    // even blocks: phase 0 (features); odd blocks: phase 1 (trajectory)
    int phase = blockIdx.x & 1;
    int pid = (blockIdx.x >> 1) * blockDim.x + tid;
    if (pid >= npairs) return;

    const float* up = u + 6 * pid;
    float u0 = up[0], u1 = up[1], u2 = up[2];
    float u3 = up[3], u4 = up[4], u5 = up[5];

    float2 x0 = make_float2(u0, u3);
    float2 x1 = make_float2(u1, u4);
    float2 x2 = make_float2(u2, u5);
    const float h   = phase ? (float)(10.0/27.0) : (float)(10.0/24.0);
    const int nseg  = phase ? 9 : 1;
    const int nsub  = phase ? 3 : 24;

    #pragma unroll 1
    for (int sg = 0; sg < nseg; sg++) {
        float t = phase ? (float)sg * (float)(10.0/9.0) : 0.0f;

        #pragma unroll 1
        for (int it = 0; it < nsub; it++) {
            float2 k[6][3];   // dynamic-indexed -> local (cheap vs compute)
            #pragma unroll 1
            for (int s = 0; s < 6; s++) {
                float2 a0 = make_float2(0.f, 0.f);
                float2 a1 = make_float2(0.f, 0.f);
                float2 a2 = make_float2(0.f, 0.f);
                int base = (s * (s - 1)) >> 1;
                for (int m = 0; m < s; m++) {
                    float a = cA[base + m];
                    a0 = f2fma(a, k[m][0], a0);
                    a1 = f2fma(a, k[m][1], a1);
                    a2 = f2fma(a, k[m][2], a2);
                }
                float2 xs0 = f2fma(h, a0, x0);
                float2 xs1 = f2fma(h, a1, x1);
                float2 xs2 = f2fma(h, a2, x2);
                float ts = fmaf(cC[s], h, t);
                dyn2(ts, xs0, xs1, xs2, k[s], sw);
            }
            float2 a0 = make_float2(0.f, 0.f);
            float2 a1 = make_float2(0.f, 0.f);
            float2 a2 = make_float2(0.f, 0.f);
            for (int m = 0; m < 6; m++) {
                float b = cB[m];
                a0 = f2fma(b, k[m][0], a0);
                a1 = f2fma(b, k[m][1], a1);
                a2 = f2fma(b, k[m][2], a2);
            }
            x0 = f2fma(h, a0, x0);
            x1 = f2fma(h, a1, x1);
            x2 = f2fma(h, a2, x2);
            t += h;
        }

        if (phase) {
            float* ot = out + (size_t)3 * B + (size_t)sg * 3 * B + 6 * pid;
            ot[0] = x0.x; ot[1] = x1.x; ot[2] = x2.x;
            ot[3] = x0.y; ot[4] = x1.y; ot[5] = x2.y;
        }
    }
    if (!phase) {
        float* of = out + 6 * pid;
        of[0] = x0.x; of[1] = x1.x; of[2] = x2.x;
        of[3] = x0.y; of[4] = x1.y; of[5] = x2.y;
    }
}

extern "C" void kernel_launch(void* const* d_in, const int* in_sizes, int n_in,
                              void* d_out, int out_size) {
    const float* u   = (const float*)d_in[0];
    const float* W1  = (const float*)d_in[1];
    const float* W2  = (const float*)d_in[2];
    const float* W3  = (const float*)d_in[3];
    const float* wb1 = (const float*)d_in[4];
    const float* bb1 = (const float*)d_in[5];
    const float* wb2 = (const float*)d_in[6];
    const float* bb2 = (const float*)d_in[7];
    const float* wb3 = (const float*)d_in[8];
    const float* bb3 = (const float*)d_in[9];
    const float* Wo1 = (const float*)d_in[10];
    const float* Wo2 = (const float*)d_in[11];
    const float* Wo3 = (const float*)d_in[12];
    float* out = (float*)d_out;
    int B = in_sizes[0] / 3;

    int npairs = B >> 1;                     // 65536
    int pblocks = (npairs + 127) / 128;      // 512
    ode_kernel<<<2 * pblocks, 128>>>(u, W1, W2, W3, wb1, bb1, wb2, bb2, wb3, bb3,
                                     Wo1, Wo2, Wo3, out, B);
}